// round 1
// baseline (speedup 1.0000x reference)
#include <cuda_runtime.h>
#include <math.h>
#include <float.h>

// Problem constants
#define Bc    2
#define Hh    64
#define Ww    160
#define DIMc  256
#define NHc   8
#define HDc   32
#define Nn    (Hh * Ww)       // 10240 tokens per batch
#define Mrows (Bc * Nn)       // 20480 total rows
#define SCALEF 0.17677669529663687f   // 32^-0.5

// Static scratch (allowed: __device__ globals, no dynamic allocation)
__device__ float g_q[Mrows * DIMc];
__device__ float g_k[Mrows * DIMc];
__device__ float g_v[Mrows * DIMc];
__device__ float g_h[Mrows * DIMc];

// ---------------------------------------------------------------------------
// SGEMM: C[M x 256] = A[M x 256] @ W[256 x 256], M = 20480.
// BM=128, BN=128, BK=8, 256 threads, 8x8 per-thread register tile.
// All dims divide tile sizes exactly -> no bounds checks.
// ---------------------------------------------------------------------------
__device__ __forceinline__ void sgemm_body(const float* __restrict__ A,
                                           const float* __restrict__ Bw,
                                           float* __restrict__ C) {
    const int Ncol = 256, Kc = 256;
    __shared__ float As[8][128];
    __shared__ float Bs[8][128];

    const int tid = threadIdx.x;
    const int tx = tid & 15;       // 0..15 (col group)
    const int ty = tid >> 4;       // 0..15 (row group)

    const float* Ab = A + (size_t)blockIdx.y * 128 * Kc;
    const float* Bb = Bw + blockIdx.x * 128;

    float acc[8][8];
#pragma unroll
    for (int i = 0; i < 8; i++)
#pragma unroll
        for (int j = 0; j < 8; j++) acc[i][j] = 0.f;

    const int arow = tid >> 1;            // 0..127
    const int acol = (tid & 1) * 4;       // 0 or 4
    const int brow = tid >> 5;            // 0..7
    const int bcol = (tid & 31) * 4;      // 0..124

    for (int k0 = 0; k0 < Kc; k0 += 8) {
        float4 a4 = *reinterpret_cast<const float4*>(Ab + (size_t)arow * Kc + k0 + acol);
        As[acol + 0][arow] = a4.x;
        As[acol + 1][arow] = a4.y;
        As[acol + 2][arow] = a4.z;
        As[acol + 3][arow] = a4.w;
        *reinterpret_cast<float4*>(&Bs[brow][bcol]) =
            *reinterpret_cast<const float4*>(Bb + (size_t)(k0 + brow) * Ncol + bcol);
        __syncthreads();

#pragma unroll
        for (int kk = 0; kk < 8; kk++) {
            float ar[8], br[8];
            *reinterpret_cast<float4*>(ar)     = *reinterpret_cast<const float4*>(&As[kk][ty * 8]);
            *reinterpret_cast<float4*>(ar + 4) = *reinterpret_cast<const float4*>(&As[kk][ty * 8 + 4]);
            *reinterpret_cast<float4*>(br)     = *reinterpret_cast<const float4*>(&Bs[kk][tx * 8]);
            *reinterpret_cast<float4*>(br + 4) = *reinterpret_cast<const float4*>(&Bs[kk][tx * 8 + 4]);
#pragma unroll
            for (int i = 0; i < 8; i++)
#pragma unroll
                for (int j = 0; j < 8; j++)
                    acc[i][j] += ar[i] * br[j];
        }
        __syncthreads();
    }

    float* Cb = C + (size_t)blockIdx.y * 128 * Ncol + blockIdx.x * 128;
#pragma unroll
    for (int i = 0; i < 8; i++) {
#pragma unroll
        for (int j = 0; j < 8; j += 4) {
            float4 o = make_float4(acc[i][j], acc[i][j + 1], acc[i][j + 2], acc[i][j + 3]);
            *reinterpret_cast<float4*>(Cb + (size_t)(ty * 8 + i) * Ncol + tx * 8 + j) = o;
        }
    }
}

__global__ void __launch_bounds__(256)
gemm_q(const float* __restrict__ X, const float* __restrict__ W) { sgemm_body(X, W, g_q); }
__global__ void __launch_bounds__(256)
gemm_k(const float* __restrict__ X, const float* __restrict__ W) { sgemm_body(X, W, g_k); }
__global__ void __launch_bounds__(256)
gemm_v(const float* __restrict__ X, const float* __restrict__ W) { sgemm_body(X, W, g_v); }
__global__ void __launch_bounds__(256)
gemm_proj(const float* __restrict__ W, float* __restrict__ out) { sgemm_body(g_h, W, out); }

// ---------------------------------------------------------------------------
// Attention: one block per token (256 threads = 8 warps = 8 heads).
// Warp w handles head w; lane d handles dim d of HD=32.
// Window: 4x4 positions around the bilinear anchor; edge rows/cols weighted
// by bilinear fractions; weighted stable softmax; weighted V sum.
// Gathers are 128 B per warp per position -> fully coalesced, L2-resident.
// ---------------------------------------------------------------------------
__global__ void __launch_bounds__(256)
attn_kernel(const float* __restrict__ mo) {
    const int r = blockIdx.x;          // global token row 0..20479
    const int b = r / Nn;
    const int warp = threadIdx.x >> 5; // head
    const int lane = threadIdx.x & 31; // dim

    // Window geometry (every lane computes for a = lane & 15; lanes 16..31 replicate)
    float ox = mo[(size_t)r * 2 + 0];
    float oy = mo[(size_t)r * 2 + 1];
    ox = fminf(fmaxf(ox, 1.0f), (float)(Ww - 2) - 0.001f);
    oy = fminf(fmaxf(oy, 1.0f), (float)(Hh - 2) - 0.001f);
    const float mx = floorf(ox), my = floorf(oy);
    const float fx = ox - mx,   fy = oy - my;

    const int a  = lane & 15;
    const int axp = a & 3;
    const int ayp = a >> 2;
    const int ix = (int)mx + axp - 1;
    const int iy = (int)my + ayp - 1;
    const int idx_a = iy * Ww + ix;    // token index within batch
    const float wxv = (axp == 0) ? (1.f - fx) : ((axp == 3) ? fx : 1.f);
    const float wyv = (ayp == 0) ? (1.f - fy) : ((ayp == 3) ? fy : 1.f);
    const float bw = wxv * wyv;

    const size_t head_off = (size_t)warp * HDc + lane;
    const float qd = g_q[(size_t)r * DIMc + head_off] * SCALEF;
    const int base_b = b * Nn;

    // Gather all 16 k/v values up front for max MLP
    float kv[16], vv[16];
#pragma unroll
    for (int aa = 0; aa < 16; aa++) {
        int ia = __shfl_sync(0xffffffffu, idx_a, aa);
        size_t off = (size_t)(base_b + ia) * DIMc + head_off;
        kv[aa] = g_k[off];
        vv[aa] = g_v[off];
    }

    // attn[a] -> held in lane a (lanes 0..15)
    float attn_mine = -FLT_MAX;
#pragma unroll
    for (int aa = 0; aa < 16; aa++) {
        float s = qd * kv[aa];
#pragma unroll
        for (int o = 16; o > 0; o >>= 1) s += __shfl_xor_sync(0xffffffffu, s, o);
        if (lane == aa) attn_mine = s;
    }

    // stable softmax over lanes 0..15 (xor offsets <=8 keep 16-groups separate)
    float m = attn_mine;
#pragma unroll
    for (int o = 8; o > 0; o >>= 1) m = fmaxf(m, __shfl_xor_sync(0xffffffffu, m, o));
    float e = (lane < 16) ? expf(attn_mine - m) * bw : 0.f;
    float se = e;
#pragma unroll
    for (int o = 8; o > 0; o >>= 1) se += __shfl_xor_sync(0xffffffffu, se, o);
    const float p = e / se;

    // out_d = sum_a p_a * v[a][d]
    float acc = 0.f;
#pragma unroll
    for (int aa = 0; aa < 16; aa++) {
        float pa = __shfl_sync(0xffffffffu, p, aa);
        acc += pa * vv[aa];
    }
    g_h[(size_t)r * DIMc + head_off] = acc;
}

// ---------------------------------------------------------------------------
extern "C" void kernel_launch(void* const* d_in, const int* in_sizes, int n_in,
                              void* d_out, int out_size) {
    const float* x  = (const float*)d_in[0];   // (B,H,W,DIM)
    const float* mo = (const float*)d_in[1];   // (B,H*W,2)
    const float* Wq = (const float*)d_in[2];
    const float* Wk = (const float*)d_in[3];
    const float* Wv = (const float*)d_in[4];
    const float* Wp = (const float*)d_in[5];
    float* out = (float*)d_out;                // (B,H,W,DIM) fp32

    dim3 gg(256 / 128, Mrows / 128);  // (2, 160)
    gemm_q<<<gg, 256>>>(x, Wq);
    gemm_k<<<gg, 256>>>(x, Wk);
    gemm_v<<<gg, 256>>>(x, Wv);
    attn_kernel<<<Mrows, 256>>>(mo);
    gemm_proj<<<gg, 256>>>(Wp, out);
}

// round 2
// speedup vs baseline: 1.4462x; 1.4462x over previous
#include <cuda_runtime.h>
#include <math.h>
#include <float.h>

// Problem constants
#define Bc    2
#define Hh    64
#define Ww    160
#define DIMc  256
#define NHc   8
#define HDc   32
#define Nn    (Hh * Ww)       // 10240 tokens per batch
#define Mrows (Bc * Nn)       // 20480 total rows
#define SCALEF 0.17677669529663687f   // 32^-0.5

// Static scratch
__device__ float g_q[Mrows * DIMc];
__device__ float g_k[Mrows * DIMc];
__device__ float g_v[Mrows * DIMc];
__device__ float g_h[Mrows * DIMc];

// ---------------------------------------------------------------------------
// tf32 helpers
// ---------------------------------------------------------------------------
__device__ __forceinline__ unsigned f2tf32(float v) {
    unsigned r;
    asm("cvt.rna.tf32.f32 %0, %1;" : "=r"(r) : "f"(v));
    return r;
}

__device__ __forceinline__ void mma1688(float c[4], const unsigned a[4], const unsigned b[2]) {
    asm volatile(
        "mma.sync.aligned.m16n8k8.row.col.f32.tf32.tf32.f32 "
        "{%0,%1,%2,%3},{%4,%5,%6,%7},{%8,%9},{%0,%1,%2,%3};"
        : "+f"(c[0]), "+f"(c[1]), "+f"(c[2]), "+f"(c[3])
        : "r"(a[0]), "r"(a[1]), "r"(a[2]), "r"(a[3]), "r"(b[0]), "r"(b[1]));
}

// ---------------------------------------------------------------------------
// 3xTF32 tensor-core GEMM: C[M x 256] = A[M x 256] @ W[256 x 256]
// BM=128, BN=128, BK=16, 512 threads (16 warps, warp tile 32x32).
// Double-buffered smem, conflict-free padded layouts.
// ---------------------------------------------------------------------------
#define KDIM 256
#define AS_STRIDE 20     // 16 + 4 pad (words): frag-load banks (20q+c)%32 all distinct
#define BS_STRIDE 136    // 128 + 8 pad: frag-load banks (8c+q+n)%32 distinct

__device__ __forceinline__ void tc_gemm_body(const float* __restrict__ A,
                                             const float* __restrict__ W,
                                             float* __restrict__ C) {
    __shared__ float As[2][128 * AS_STRIDE];   // [m][k] layout
    __shared__ float Bs[2][16 * BS_STRIDE];    // [k][n] layout

    const int t    = threadIdx.x;
    const int warp = t >> 5;
    const int lane = t & 31;
    const int q    = lane >> 2;   // 0..7
    const int c4   = lane & 3;    // 0..3

    const int bm = blockIdx.y * 128;
    const int bn = blockIdx.x * 128;
    const int wm = (warp >> 2) * 32;   // warp row offset in tile
    const int wn = (warp & 3) * 32;    // warp col offset in tile

    // G->S staging indices
    const int arow = t >> 2;           // 0..127
    const int acg  = (t & 3) * 4;      // 0,4,8,12
    const int brow = t >> 5;           // 0..15
    const int bcol = (t & 31) * 4;     // 0..124

    const float* Ag = A + (size_t)(bm + arow) * KDIM + acg;
    const float* Bg = W + (size_t)brow * KDIM + bn + bcol;

    float acc[2][4][4];
#pragma unroll
    for (int i = 0; i < 2; i++)
#pragma unroll
        for (int j = 0; j < 4; j++)
#pragma unroll
            for (int e = 0; e < 4; e++) acc[i][j][e] = 0.f;

    // prologue: tile 0
    float4 areg = *reinterpret_cast<const float4*>(Ag);
    float4 breg = *reinterpret_cast<const float4*>(Bg);
    *reinterpret_cast<float4*>(&As[0][arow * AS_STRIDE + acg]) = areg;
    *reinterpret_cast<float4*>(&Bs[0][brow * BS_STRIDE + bcol]) = breg;
    __syncthreads();

#pragma unroll 1
    for (int it = 0; it < 16; ++it) {
        const int cur = it & 1;
        if (it < 15) {
            areg = *reinterpret_cast<const float4*>(Ag + (it + 1) * 16);
            breg = *reinterpret_cast<const float4*>(Bg + (size_t)(it + 1) * 16 * KDIM);
        }

#pragma unroll
        for (int ks = 0; ks < 16; ks += 8) {
            // A fragments (2 m-tiles), hi/lo split
            unsigned ahi[2][4], alo[2][4];
#pragma unroll
            for (int i = 0; i < 2; i++) {
                const int mb = wm + i * 16;
                float v0 = As[cur][(mb + q)     * AS_STRIDE + ks + c4];
                float v1 = As[cur][(mb + q + 8) * AS_STRIDE + ks + c4];
                float v2 = As[cur][(mb + q)     * AS_STRIDE + ks + c4 + 4];
                float v3 = As[cur][(mb + q + 8) * AS_STRIDE + ks + c4 + 4];
                ahi[i][0] = f2tf32(v0); alo[i][0] = f2tf32(v0 - __uint_as_float(ahi[i][0]));
                ahi[i][1] = f2tf32(v1); alo[i][1] = f2tf32(v1 - __uint_as_float(ahi[i][1]));
                ahi[i][2] = f2tf32(v2); alo[i][2] = f2tf32(v2 - __uint_as_float(ahi[i][2]));
                ahi[i][3] = f2tf32(v3); alo[i][3] = f2tf32(v3 - __uint_as_float(ahi[i][3]));
            }
            // B fragments (4 n-tiles), hi/lo split
            unsigned bhi[4][2], blo[4][2];
#pragma unroll
            for (int j = 0; j < 4; j++) {
                const int nb = wn + j * 8 + q;
                float w0 = Bs[cur][(ks + c4)     * BS_STRIDE + nb];
                float w1 = Bs[cur][(ks + c4 + 4) * BS_STRIDE + nb];
                bhi[j][0] = f2tf32(w0); blo[j][0] = f2tf32(w0 - __uint_as_float(bhi[j][0]));
                bhi[j][1] = f2tf32(w1); blo[j][1] = f2tf32(w1 - __uint_as_float(bhi[j][1]));
            }
            // 3xTF32 MMAs
#pragma unroll
            for (int i = 0; i < 2; i++)
#pragma unroll
                for (int j = 0; j < 4; j++) {
                    mma1688(acc[i][j], ahi[i], blo[j]);
                    mma1688(acc[i][j], alo[i], bhi[j]);
                    mma1688(acc[i][j], ahi[i], bhi[j]);
                }
        }

        if (it < 15) {
            const int nxt = cur ^ 1;
            *reinterpret_cast<float4*>(&As[nxt][arow * AS_STRIDE + acg]) = areg;
            *reinterpret_cast<float4*>(&Bs[nxt][brow * BS_STRIDE + bcol]) = breg;
            __syncthreads();
        }
    }

    // Epilogue: warp tile 32x32 -> global
#pragma unroll
    for (int i = 0; i < 2; i++) {
#pragma unroll
        for (int j = 0; j < 4; j++) {
            const int gr0 = bm + wm + i * 16 + q;
            const int gc  = bn + wn + j * 8 + 2 * c4;
            *reinterpret_cast<float2*>(C + (size_t)gr0 * KDIM + gc) =
                make_float2(acc[i][j][0], acc[i][j][1]);
            *reinterpret_cast<float2*>(C + (size_t)(gr0 + 8) * KDIM + gc) =
                make_float2(acc[i][j][2], acc[i][j][3]);
        }
    }
}

// QKV fused over blockIdx.z
__global__ void __launch_bounds__(512, 1)
gemm_qkv(const float* __restrict__ X,
         const float* __restrict__ Wq, const float* __restrict__ Wk,
         const float* __restrict__ Wv) {
    const float* W = (blockIdx.z == 0) ? Wq : (blockIdx.z == 1) ? Wk : Wv;
    float* C = (blockIdx.z == 0) ? g_q : (blockIdx.z == 1) ? g_k : g_v;
    tc_gemm_body(X, W, C);
}

__global__ void __launch_bounds__(512, 1)
gemm_proj(const float* __restrict__ W, float* __restrict__ out) {
    tc_gemm_body(g_h, W, out);
}

// ---------------------------------------------------------------------------
// Attention: one block per token (8 warps = 8 heads), lane = dim.
// ---------------------------------------------------------------------------
__global__ void __launch_bounds__(256)
attn_kernel(const float* __restrict__ mo) {
    const int r = blockIdx.x;
    const int b = r / Nn;
    const int warp = threadIdx.x >> 5;
    const int lane = threadIdx.x & 31;

    float ox = mo[(size_t)r * 2 + 0];
    float oy = mo[(size_t)r * 2 + 1];
    ox = fminf(fmaxf(ox, 1.0f), (float)(Ww - 2) - 0.001f);
    oy = fminf(fmaxf(oy, 1.0f), (float)(Hh - 2) - 0.001f);
    const float mx = floorf(ox), my = floorf(oy);
    const float fx = ox - mx,   fy = oy - my;

    const int a   = lane & 15;
    const int axp = a & 3;
    const int ayp = a >> 2;
    const int ix = (int)mx + axp - 1;
    const int iy = (int)my + ayp - 1;
    const int idx_a = iy * Ww + ix;
    const float wxv = (axp == 0) ? (1.f - fx) : ((axp == 3) ? fx : 1.f);
    const float wyv = (ayp == 0) ? (1.f - fy) : ((ayp == 3) ? fy : 1.f);
    const float bw = wxv * wyv;

    const size_t head_off = (size_t)warp * HDc + lane;
    const float qd = g_q[(size_t)r * DIMc + head_off] * SCALEF;
    const int base_b = b * Nn;

    float kv[16], vv[16];
#pragma unroll
    for (int aa = 0; aa < 16; aa++) {
        int ia = __shfl_sync(0xffffffffu, idx_a, aa);
        size_t off = (size_t)(base_b + ia) * DIMc + head_off;
        kv[aa] = g_k[off];
        vv[aa] = g_v[off];
    }

    float attn_mine = -FLT_MAX;
#pragma unroll
    for (int aa = 0; aa < 16; aa++) {
        float s = qd * kv[aa];
#pragma unroll
        for (int o = 16; o > 0; o >>= 1) s += __shfl_xor_sync(0xffffffffu, s, o);
        if (lane == aa) attn_mine = s;
    }

    float m = attn_mine;
#pragma unroll
    for (int o = 8; o > 0; o >>= 1) m = fmaxf(m, __shfl_xor_sync(0xffffffffu, m, o));
    float e = (lane < 16) ? expf(attn_mine - m) * bw : 0.f;
    float se = e;
#pragma unroll
    for (int o = 8; o > 0; o >>= 1) se += __shfl_xor_sync(0xffffffffu, se, o);
    const float p = e / se;

    float accv = 0.f;
#pragma unroll
    for (int aa = 0; aa < 16; aa++) {
        float pa = __shfl_sync(0xffffffffu, p, aa);
        accv += pa * vv[aa];
    }
    g_h[(size_t)r * DIMc + head_off] = accv;
}

// ---------------------------------------------------------------------------
extern "C" void kernel_launch(void* const* d_in, const int* in_sizes, int n_in,
                              void* d_out, int out_size) {
    const float* x  = (const float*)d_in[0];
    const float* mo = (const float*)d_in[1];
    const float* Wq = (const float*)d_in[2];
    const float* Wk = (const float*)d_in[3];
    const float* Wv = (const float*)d_in[4];
    const float* Wp = (const float*)d_in[5];
    float* out = (float*)d_out;

    dim3 gqkv(256 / 128, Mrows / 128, 3);   // (2, 160, 3)
    gemm_qkv<<<gqkv, 512>>>(x, Wq, Wk, Wv);
    attn_kernel<<<Mrows, 256>>>(mo);
    dim3 gp(256 / 128, Mrows / 128);        // (2, 160)
    gemm_proj<<<gp, 512>>>(Wp, out);
}